// round 5
// baseline (speedup 1.0000x reference)
#include <cuda_runtime.h>
#include <cstdint>

#define N_TOOLS 50
#define DIM 512
#define N_TOKENS 8192
#define PARAM_DIM 256
#define BK 16
#define KSTAGES (DIM / BK)   // 32

// --------------------- device scratch (no allocs allowed) ------------------
__device__ int g_count[N_TOOLS];
__device__ int g_tokens[N_TOOLS * N_TOKENS];
__device__ int g_ntiles;
__device__ int g_tile_e[256];
__device__ int g_tile_m[256];

__global__ void zero_counts_kernel() {
    if (threadIdx.x < N_TOOLS) g_count[threadIdx.x] = 0;
}

// Compact (expert, mtile) work list for the adapted GEMM (BM=64 tiles).
__global__ void build_tiles_kernel() {
    if (threadIdx.x == 0) {
        int t = 0;
        for (int e = 0; e < N_TOOLS; e++) {
            int tiles = (g_count[e] + 63) >> 6;
            for (int m = 0; m < tiles; m++) {
                g_tile_e[t] = e;
                g_tile_m[t] = m;
                t++;
            }
        }
        g_ntiles = t;
    }
}

// ----------------------------- helpers ------------------------------------
__device__ __forceinline__ uint32_t f2tf32(float x) {
    uint32_t r;
    asm("cvt.rna.tf32.f32 %0, %1;" : "=r"(r) : "f"(x));
    return r;
}
__device__ __forceinline__ void mma_tf32(float* c, uint32_t a0, uint32_t a1,
                                         uint32_t a2, uint32_t a3,
                                         uint32_t b0, uint32_t b1) {
    asm volatile(
        "mma.sync.aligned.m16n8k8.row.col.f32.tf32.tf32.f32 "
        "{%0,%1,%2,%3}, {%4,%5,%6,%7}, {%8,%9}, {%0,%1,%2,%3};"
        : "+f"(c[0]), "+f"(c[1]), "+f"(c[2]), "+f"(c[3])
        : "r"(a0), "r"(a1), "r"(a2), "r"(a3), "r"(b0), "r"(b1));
}

// ======================= router (exact fp32) ==============================
__global__ void router_kernel(const float* __restrict__ x,
                              const float* __restrict__ rw,
                              const float* __restrict__ rb,
                              float* __restrict__ out_idx,
                              float* __restrict__ out_probs) {
    __shared__ float Xs[32][64];
    __shared__ float Ws[N_TOOLS][32];
    __shared__ float Ls[64][52];
    __shared__ float Bs[N_TOOLS];

    const int tid = threadIdx.x;
    const int row0 = blockIdx.x * 64;
    if (tid < N_TOOLS) Bs[tid] = rb[tid];

    const int rm = tid >> 1;
    const int half = (tid & 1) * 25;
    float acc[25];
#pragma unroll
    for (int j = 0; j < 25; j++) acc[j] = 0.f;

    for (int k0 = 0; k0 < DIM; k0 += 32) {
        __syncthreads();
#pragma unroll
        for (int t = 0; t < 4; t++) {
            int j = tid + t * 128;
            int m = j >> 3, kq = (j & 7) * 4;
            float4 v = *(const float4*)&x[(size_t)(row0 + m) * DIM + k0 + kq];
            Xs[kq + 0][m] = v.x; Xs[kq + 1][m] = v.y;
            Xs[kq + 2][m] = v.z; Xs[kq + 3][m] = v.w;
        }
        for (int j = tid; j < 400; j += 128) {
            int n = j >> 3, kq = (j & 7) * 4;
            float4 v = *(const float4*)&rw[(size_t)n * DIM + k0 + kq];
            Ws[n][kq + 0] = v.x; Ws[n][kq + 1] = v.y;
            Ws[n][kq + 2] = v.z; Ws[n][kq + 3] = v.w;
        }
        __syncthreads();
#pragma unroll
        for (int k = 0; k < 32; k++) {
            float xv = Xs[k][rm];
#pragma unroll
            for (int j = 0; j < 25; j++) acc[j] += xv * Ws[half + j][k];
        }
    }
#pragma unroll
    for (int j = 0; j < 25; j++) Ls[rm][half + j] = acc[j];
    __syncthreads();

    if (tid < 64) {
        const int row = row0 + tid;
        float lg[N_TOOLS];
        float best = -1e30f;
        int bi = 0;
#pragma unroll
        for (int j = 0; j < N_TOOLS; j++) {
            float v = Ls[tid][j] + Bs[j];
            lg[j] = v;
            if (v > best) { best = v; bi = j; }
        }
        float s = 0.f;
#pragma unroll
        for (int j = 0; j < N_TOOLS; j++) { lg[j] = expf(lg[j] - best); s += lg[j]; }
        float inv = 1.f / s;
#pragma unroll
        for (int j = 0; j < N_TOOLS; j++)
            out_probs[(size_t)row * N_TOOLS + j] = lg[j] * inv;
        out_idx[row] = (float)bi;
        int pos = atomicAdd(&g_count[bi], 1);
        g_tokens[bi * N_TOKENS + pos] = row;
    }
}

// ======================= tf32 tensor-core GEMM ============================
// Y[64, BN] = X @ W^T + b.  Warp tile 32x64 (2 m-frags x 8 n-frags).
// NTHR/32 warps laid out as 2m x (NTHR/64)n.
// SMEM layout (BK=16, 16 words/row, no pad):
//   logical k-word c of row r at: r*16 + 4*((c&3) ^ ((r>>1)&3)) + (c>>2)
//   -> LDS.128 delivers k = {tg, tg+4, tg+8, tg+12} (one k16 of frags), CF.
//   -> STS.32 with warp = 8 rows x 4 quads tiles all 32 banks, CF.
template <int BN, int NTHR, int MINCTA, bool GATHER>
__global__ void __launch_bounds__(NTHR, MINCTA)
tc_gemm(const float* __restrict__ X, const float* __restrict__ Wg,
        const float* __restrict__ Bg, float* __restrict__ out, int out_ld) {
    constexpr int BM = 64;
    constexpr int STAGE = (BM + BN) * 16;
    constexpr int NA = BM * 4 / NTHR;
    constexpr int NB = BN * 4 / NTHR;

    __shared__ uint32_t sm[2][STAGE];
    __shared__ float bsh[BN];
    __shared__ int ridx[BM];

    const int tid = threadIdx.x;
    const int lane = tid & 31, warp = tid >> 5;
    const int g = lane >> 2, tg = lane & 3;
    const int wm = (warp & 1) * 32;
    const int wn = (warp >> 1) * 64;
    const int n0 = blockIdx.x * BN;

    const float* W;
    const float* bsrc;
    int row0 = 0;

    if (GATHER) {
        const int ty = blockIdx.y;
        if (ty >= g_ntiles) return;
        const int e = g_tile_e[ty];
        const int mtile = g_tile_m[ty];
        const int cnt = g_count[e];
        W = Wg + (size_t)e * DIM * DIM + (size_t)n0 * DIM;
        bsrc = Bg + (size_t)e * DIM;
        if (tid < BM) {
            int p = mtile * BM + tid;
            ridx[tid] = g_tokens[e * N_TOKENS + (p < cnt ? p : cnt - 1)];
        }
    } else {
        W = Wg + (size_t)n0 * DIM;
        bsrc = Bg;
        row0 = blockIdx.y * BM;
    }
    for (int i = tid; i < BN; i += NTHR) bsh[i] = bsrc[n0 + i];
    __syncthreads();

    // ---- loader setup: element e -> (r = 8*(e>>5)+(e&7), q = (e>>3)&3) ----
    int agoff[NA], asmb[NA], ap[NA];
    int bgoff[NB], bsmb[NB], bp[NB];
#pragma unroll
    for (int i = 0; i < NA; i++) {
        int e = tid + NTHR * i;
        int r = ((e >> 5) << 3) + (e & 7);
        int q = (e >> 3) & 3;
        int gr = GATHER ? ridx[r] : row0 + r;
        agoff[i] = gr * DIM + q * 4;
        asmb[i] = r * 16 + q;
        ap[i] = (r >> 1) & 3;
    }
#pragma unroll
    for (int i = 0; i < NB; i++) {
        int e = tid + NTHR * i;
        int r = ((e >> 5) << 3) + (e & 7);
        int q = (e >> 3) & 3;
        bgoff[i] = r * DIM + q * 4;
        bsmb[i] = BM * 16 + r * 16 + q;
        bp[i] = (r >> 1) & 3;
    }

    // ---- frag smem offsets (k-invariant) ----
    int offA[2][2], offB[8];
#pragma unroll
    for (int mt = 0; mt < 2; mt++) {
        int rA = wm + mt * 16 + g;
        offA[mt][0] = rA * 16 + ((tg ^ ((rA >> 1) & 3)) << 2);
        rA += 8;
        offA[mt][1] = rA * 16 + ((tg ^ ((rA >> 1) & 3)) << 2);
    }
#pragma unroll
    for (int nt = 0; nt < 8; nt++) {
        int rB = wn + nt * 8 + g;
        offB[nt] = BM * 16 + rB * 16 + ((tg ^ ((rB >> 1) & 3)) << 2);
    }

    float acc[2][8][4];
#pragma unroll
    for (int mt = 0; mt < 2; mt++)
#pragma unroll
        for (int nt = 0; nt < 8; nt++)
#pragma unroll
            for (int i = 0; i < 4; i++) acc[mt][nt][i] = 0.f;

    // ---- fill stage 0 ----
    {
        uint32_t* S = sm[0];
#pragma unroll
        for (int i = 0; i < NA; i++) {
            float4 v = *(const float4*)(X + agoff[i]);
            S[asmb[i] + ((0 ^ ap[i]) << 2)] = f2tf32(v.x);
            S[asmb[i] + ((1 ^ ap[i]) << 2)] = f2tf32(v.y);
            S[asmb[i] + ((2 ^ ap[i]) << 2)] = f2tf32(v.z);
            S[asmb[i] + ((3 ^ ap[i]) << 2)] = f2tf32(v.w);
        }
#pragma unroll
        for (int i = 0; i < NB; i++) {
            float4 v = *(const float4*)(W + bgoff[i]);
            S[bsmb[i] + ((0 ^ bp[i]) << 2)] = f2tf32(v.x);
            S[bsmb[i] + ((1 ^ bp[i]) << 2)] = f2tf32(v.y);
            S[bsmb[i] + ((2 ^ bp[i]) << 2)] = f2tf32(v.z);
            S[bsmb[i] + ((3 ^ bp[i]) << 2)] = f2tf32(v.w);
        }
    }
    __syncthreads();

    for (int kt = 0; kt < KSTAGES; kt++) {
        const uint32_t* S = sm[kt & 1];
        float4 pa[NA], pb[NB];
        if (kt + 1 < KSTAGES) {
            const int ko = (kt + 1) * BK;
#pragma unroll
            for (int i = 0; i < NA; i++) pa[i] = *(const float4*)(X + agoff[i] + ko);
#pragma unroll
            for (int i = 0; i < NB; i++) pb[i] = *(const float4*)(W + bgoff[i] + ko);
        }

        uint4 va[2][2];
#pragma unroll
        for (int mt = 0; mt < 2; mt++) {
            va[mt][0] = *(const uint4*)&S[offA[mt][0]];
            va[mt][1] = *(const uint4*)&S[offA[mt][1]];
        }
#pragma unroll
        for (int nt = 0; nt < 8; nt++) {
            uint4 vb = *(const uint4*)&S[offB[nt]];
#pragma unroll
            for (int mt = 0; mt < 2; mt++) {
                mma_tf32(acc[mt][nt], va[mt][0].x, va[mt][1].x,
                         va[mt][0].y, va[mt][1].y, vb.x, vb.y);
                mma_tf32(acc[mt][nt], va[mt][0].z, va[mt][1].z,
                         va[mt][0].w, va[mt][1].w, vb.z, vb.w);
            }
        }

        if (kt + 1 < KSTAGES) {
            uint32_t* D = sm[(kt + 1) & 1];
#pragma unroll
            for (int i = 0; i < NA; i++) {
                D[asmb[i] + ((0 ^ ap[i]) << 2)] = f2tf32(pa[i].x);
                D[asmb[i] + ((1 ^ ap[i]) << 2)] = f2tf32(pa[i].y);
                D[asmb[i] + ((2 ^ ap[i]) << 2)] = f2tf32(pa[i].z);
                D[asmb[i] + ((3 ^ ap[i]) << 2)] = f2tf32(pa[i].w);
            }
#pragma unroll
            for (int i = 0; i < NB; i++) {
                D[bsmb[i] + ((0 ^ bp[i]) << 2)] = f2tf32(pb[i].x);
                D[bsmb[i] + ((1 ^ bp[i]) << 2)] = f2tf32(pb[i].y);
                D[bsmb[i] + ((2 ^ bp[i]) << 2)] = f2tf32(pb[i].z);
                D[bsmb[i] + ((3 ^ bp[i]) << 2)] = f2tf32(pb[i].w);
            }
        }
        __syncthreads();
    }

    // ---- epilogue: bias + store (padded duplicate rows write identical
    //      values -> deterministic) ----
#pragma unroll
    for (int mt = 0; mt < 2; mt++) {
        const int lr0 = wm + mt * 16 + g;
        const int lr1 = lr0 + 8;
        const int gr0 = GATHER ? ridx[lr0] : row0 + lr0;
        const int gr1 = GATHER ? ridx[lr1] : row0 + lr1;
        float* o0 = out + (size_t)gr0 * out_ld + n0;
        float* o1 = out + (size_t)gr1 * out_ld + n0;
#pragma unroll
        for (int nt = 0; nt < 8; nt++) {
            const int c = wn + nt * 8 + 2 * tg;
            float2 s0, s1;
            s0.x = acc[mt][nt][0] + bsh[c];
            s0.y = acc[mt][nt][1] + bsh[c + 1];
            s1.x = acc[mt][nt][2] + bsh[c];
            s1.y = acc[mt][nt][3] + bsh[c + 1];
            *(float2*)(o0 + c) = s0;
            *(float2*)(o1 + c) = s1;
        }
    }
}

// ===========================================================================
extern "C" void kernel_launch(void* const* d_in, const int* in_sizes, int n_in,
                              void* d_out, int out_size) {
    const float* x  = (const float*)d_in[0];
    const float* rw = (const float*)d_in[1];
    const float* rb = (const float*)d_in[2];
    const float* ew = (const float*)d_in[3];
    const float* eb = (const float*)d_in[4];
    const float* pw = (const float*)d_in[5];
    const float* pb = (const float*)d_in[6];

    float* out      = (float*)d_out;
    float* o_idx    = out;
    float* o_probs  = out + N_TOKENS;
    float* o_adapt  = o_probs + (size_t)N_TOKENS * N_TOOLS;
    float* o_params = o_adapt + (size_t)N_TOKENS * DIM;

    zero_counts_kernel<<<1, 64>>>();
    router_kernel<<<N_TOKENS / 64, 128>>>(x, rw, rb, o_idx, o_probs);
    build_tiles_kernel<<<1, 32>>>();
    // params: BM=64, BN=128, 128 threads (4 warps, 2m x 2n of 32x64)
    tc_gemm<128, 128, 4, false>
        <<<dim3(PARAM_DIM / 128, N_TOKENS / 64), 128>>>(x, pw, pb, o_params,
                                                        PARAM_DIM);
    // adapted: BM=64, BN=256, 256 threads (8 warps, 2m x 4n of 32x64)
    // max tiles = 8192/64 + 49 = 177
    tc_gemm<256, 256, 2, true>
        <<<dim3(DIM / 256, 177), 256>>>(x, ew, eb, o_adapt, DIM);
}

// round 6
// speedup vs baseline: 2.2007x; 2.2007x over previous
#include <cuda_runtime.h>
#include <cstdint>

#define N_TOOLS 50
#define DIM 512
#define N_TOKENS 8192
#define PARAM_DIM 256

#define BM 64
#define BN 256
#define BK 16
#define STAGES 4
#define SWORDS ((BM + BN) * BK)      // 5120 words / stage
#define NTHR 128
#define PCTAS (N_TOKENS / BM)        // 128
#define MAXTILES 178                 // sum ceil(cnt/64) <= 128 + 50
#define KITERS (DIM / BK)            // 32

// --------------------- device scratch (no allocs allowed) ------------------
__device__ int g_count[N_TOOLS];
__device__ int g_tokens[N_TOOLS * N_TOKENS];
__device__ int g_ntiles;
__device__ int g_tile_e[256];
__device__ int g_tile_m[256];

__global__ void zero_counts_kernel() {
    if (threadIdx.x < N_TOOLS) g_count[threadIdx.x] = 0;
}

__global__ void build_tiles_kernel() {
    if (threadIdx.x == 0) {
        int t = 0;
        for (int e = 0; e < N_TOOLS; e++) {
            int tiles = (g_count[e] + BM - 1) / BM;
            for (int m = 0; m < tiles; m++) {
                g_tile_e[t] = e;
                g_tile_m[t] = m;
                t++;
            }
        }
        g_ntiles = t;
    }
}

// ----------------------------- helpers ------------------------------------
__device__ __forceinline__ uint32_t f2tf32(float x) {
    uint32_t r;
    asm("cvt.rna.tf32.f32 %0, %1;" : "=r"(r) : "f"(x));
    return r;
}
__device__ __forceinline__ void mma_tf32(float* c, uint32_t a0, uint32_t a1,
                                         uint32_t a2, uint32_t a3,
                                         uint32_t b0, uint32_t b1) {
    asm volatile(
        "mma.sync.aligned.m16n8k8.row.col.f32.tf32.tf32.f32 "
        "{%0,%1,%2,%3}, {%4,%5,%6,%7}, {%8,%9}, {%0,%1,%2,%3};"
        : "+f"(c[0]), "+f"(c[1]), "+f"(c[2]), "+f"(c[3])
        : "r"(a0), "r"(a1), "r"(a2), "r"(a3), "r"(b0), "r"(b1));
}
__device__ __forceinline__ uint32_t smem_u32(const void* p) {
    uint32_t a;
    asm("{ .reg .u64 t; cvta.to.shared.u64 t, %1; cvt.u32.u64 %0, t; }"
        : "=r"(a) : "l"(p));
    return a;
}
__device__ __forceinline__ void cp16(uint32_t dst, const float* src) {
    asm volatile("cp.async.cg.shared.global [%0], [%1], 16;"
                 :: "r"(dst), "l"(src) : "memory");
}
#define CP_COMMIT() asm volatile("cp.async.commit_group;" ::: "memory")
#define CP_WAIT2()  asm volatile("cp.async.wait_group 2;" ::: "memory")

// ======================= router (exact fp32) ==============================
__global__ void router_kernel(const float* __restrict__ x,
                              const float* __restrict__ rw,
                              const float* __restrict__ rb,
                              float* __restrict__ out_idx,
                              float* __restrict__ out_probs) {
    __shared__ float Xs[32][64];
    __shared__ float Ws[N_TOOLS][32];
    __shared__ float Ls[64][52];
    __shared__ float Bs[N_TOOLS];

    const int tid = threadIdx.x;
    const int row0 = blockIdx.x * 64;
    if (tid < N_TOOLS) Bs[tid] = rb[tid];

    const int rm = tid >> 1;
    const int half = (tid & 1) * 25;
    float acc[25];
#pragma unroll
    for (int j = 0; j < 25; j++) acc[j] = 0.f;

    for (int k0 = 0; k0 < DIM; k0 += 32) {
        __syncthreads();
#pragma unroll
        for (int t = 0; t < 4; t++) {
            int j = tid + t * 128;
            int m = j >> 3, kq = (j & 7) * 4;
            float4 v = *(const float4*)&x[(size_t)(row0 + m) * DIM + k0 + kq];
            Xs[kq + 0][m] = v.x; Xs[kq + 1][m] = v.y;
            Xs[kq + 2][m] = v.z; Xs[kq + 3][m] = v.w;
        }
        for (int j = tid; j < 400; j += 128) {
            int n = j >> 3, kq = (j & 7) * 4;
            float4 v = *(const float4*)&rw[(size_t)n * DIM + k0 + kq];
            Ws[n][kq + 0] = v.x; Ws[n][kq + 1] = v.y;
            Ws[n][kq + 2] = v.z; Ws[n][kq + 3] = v.w;
        }
        __syncthreads();
#pragma unroll
        for (int k = 0; k < 32; k++) {
            float xv = Xs[k][rm];
#pragma unroll
            for (int j = 0; j < 25; j++) acc[j] += xv * Ws[half + j][k];
        }
    }
#pragma unroll
    for (int j = 0; j < 25; j++) Ls[rm][half + j] = acc[j];
    __syncthreads();

    if (tid < 64) {
        const int row = row0 + tid;
        float lg[N_TOOLS];
        float best = -1e30f;
        int bi = 0;
#pragma unroll
        for (int j = 0; j < N_TOOLS; j++) {
            float v = Ls[tid][j] + Bs[j];
            lg[j] = v;
            if (v > best) { best = v; bi = j; }
        }
        float s = 0.f;
#pragma unroll
        for (int j = 0; j < N_TOOLS; j++) { lg[j] = expf(lg[j] - best); s += lg[j]; }
        float inv = 1.f / s;
#pragma unroll
        for (int j = 0; j < N_TOOLS; j++)
            out_probs[(size_t)row * N_TOOLS + j] = lg[j] * inv;
        out_idx[row] = (float)bi;
        int pos = atomicAdd(&g_count[bi], 1);
        g_tokens[bi * N_TOKENS + pos] = row;
    }
}

// ================== merged tf32 tensor-core GEMM ===========================
// CTA: 64x256 tile of Y = X @ W^T + b.  4 warps, each 64x64 (4m x 8n frags).
// cp.async 4-stage pipeline, BK=16.  First PCTAS blocks: dense params GEMM;
// rest: gathered expert GEMM over the compacted (expert, mtile) list.
// SMEM: chunk q (16B) of row r stored at chunk (q ^ ((r>>1)&3)) ->
//   conflict-free scalar LDS for all mma fragments.
extern __shared__ uint32_t dynsm[];

__global__ void __launch_bounds__(NTHR, 2)
moe_gemm(const float* __restrict__ X, const float* __restrict__ pw,
         const float* __restrict__ pb, const float* __restrict__ ew,
         const float* __restrict__ eb, float* __restrict__ o_params,
         float* __restrict__ o_adapt) {
    uint32_t* sm = dynsm;
    float* bsh = (float*)(dynsm + STAGES * SWORDS);
    int* ridx = (int*)(bsh + BN);

    const int tid = threadIdx.x;
    const int lane = tid & 31, warp = tid >> 5;
    const int g = lane >> 2, tg = lane & 3;

    const float* W;
    const float* bsrc;
    float* outbase;
    int out_ld, n0, row0 = 0;
    bool gather;

    if (blockIdx.x < PCTAS) {
        gather = false;
        row0 = blockIdx.x * BM;
        W = pw; bsrc = pb;
        outbase = o_params; out_ld = PARAM_DIM; n0 = 0;
    } else {
        gather = true;
        const int t = blockIdx.x - PCTAS;
        const int ty = t >> 1;
        if (ty >= g_ntiles) return;
        n0 = (t & 1) * BN;
        const int e = g_tile_e[ty];
        const int mtile = g_tile_m[ty];
        const int cnt = g_count[e];
        W = ew + (size_t)e * DIM * DIM + (size_t)n0 * DIM;
        bsrc = eb + (size_t)e * DIM + n0;
        outbase = o_adapt; out_ld = DIM;
        if (tid < BM) {
            int p = mtile * BM + tid;
            ridx[tid] = g_tokens[e * N_TOKENS + (p < cnt ? p : cnt - 1)];
        }
    }
    for (int i = tid; i < BN; i += NTHR) bsh[i] = bsrc[i];
    __syncthreads();

    // ---- cp.async setup: thread covers chunk q of rows r0 + 32*i ----
    const uint32_t smbase = smem_u32(dynsm);
    const int r0 = tid >> 2, q = tid & 3;
    const int ph = (r0 >> 1) & 3;
    const uint32_t dst0 = smbase + ((uint32_t)(r0 * 16 + ((q ^ ph) << 2)) << 2);

    const int ar0 = gather ? ridx[r0] : row0 + r0;
    const int ar1 = gather ? ridx[r0 + 32] : row0 + r0 + 32;
    const float* srcA0 = X + (size_t)ar0 * DIM + q * 4;
    const float* srcA1 = X + (size_t)ar1 * DIM + q * 4;
    const float* srcB = W + (size_t)r0 * DIM + q * 4;

#define ISSUE(s, ko) do {                                                    \
        uint32_t d = dst0 + (uint32_t)(s) * (SWORDS * 4);                    \
        cp16(d, srcA0 + (ko));                                               \
        cp16(d + 2048, srcA1 + (ko));                                        \
        _Pragma("unroll")                                                    \
        for (int j = 0; j < 8; j++)                                          \
            cp16(d + 4096 + j * 2048, srcB + j * (32 * DIM) + (ko));         \
        CP_COMMIT();                                                         \
    } while (0)

    ISSUE(0, 0);
    ISSUE(1, BK);
    ISSUE(2, 2 * BK);

    float acc[4][8][4];
#pragma unroll
    for (int mt = 0; mt < 4; mt++)
#pragma unroll
        for (int nt = 0; nt < 8; nt++)
#pragma unroll
            for (int i = 0; i < 4; i++) acc[mt][nt][i] = 0.f;

    const int wn = warp * 64;

    for (int kt = 0; kt < KITERS; kt++) {
        CP_WAIT2();
        __syncthreads();
        if (kt + 3 < KITERS) {
            ISSUE((kt + 3) & 3, (kt + 3) * BK);
        } else {
            CP_COMMIT();
        }
        const uint32_t* S = sm + (kt & 3) * SWORDS;

#pragma unroll
        for (int h = 0; h < 2; h++) {
            uint32_t a[4][4];
#pragma unroll
            for (int mt = 0; mt < 4; mt++) {
                const int ra = mt * 16 + g;
                const int pa = (ra >> 1) & 3;
                const int rb = ra + 8;
                const int pb2 = (rb >> 1) & 3;
                a[mt][0] = f2tf32(__uint_as_float(
                    S[ra * 16 + (((2 * h) ^ pa) << 2) + tg]));
                a[mt][1] = f2tf32(__uint_as_float(
                    S[rb * 16 + (((2 * h) ^ pb2) << 2) + tg]));
                a[mt][2] = f2tf32(__uint_as_float(
                    S[ra * 16 + (((2 * h + 1) ^ pa) << 2) + tg]));
                a[mt][3] = f2tf32(__uint_as_float(
                    S[rb * 16 + (((2 * h + 1) ^ pb2) << 2) + tg]));
            }
#pragma unroll
            for (int nt = 0; nt < 8; nt++) {
                const int rn = BM + wn + nt * 8 + g;
                const int pn = (rn >> 1) & 3;
                const uint32_t b0 = f2tf32(__uint_as_float(
                    S[rn * 16 + (((2 * h) ^ pn) << 2) + tg]));
                const uint32_t b1 = f2tf32(__uint_as_float(
                    S[rn * 16 + (((2 * h + 1) ^ pn) << 2) + tg]));
#pragma unroll
                for (int mt = 0; mt < 4; mt++)
                    mma_tf32(acc[mt][nt], a[mt][0], a[mt][1], a[mt][2],
                             a[mt][3], b0, b1);
            }
        }
    }

    // ---- epilogue: bias + store (duplicate padded rows write identical
    //      values -> deterministic) ----
#pragma unroll
    for (int mt = 0; mt < 4; mt++) {
        const int lr0 = mt * 16 + g;
        const int lr1 = lr0 + 8;
        const int gr0 = gather ? ridx[lr0] : row0 + lr0;
        const int gr1 = gather ? ridx[lr1] : row0 + lr1;
        float* o0 = outbase + (size_t)gr0 * out_ld + n0;
        float* o1 = outbase + (size_t)gr1 * out_ld + n0;
#pragma unroll
        for (int nt = 0; nt < 8; nt++) {
            const int c = wn + nt * 8 + 2 * tg;
            float2 s0, s1;
            s0.x = acc[mt][nt][0] + bsh[c];
            s0.y = acc[mt][nt][1] + bsh[c + 1];
            s1.x = acc[mt][nt][2] + bsh[c];
            s1.y = acc[mt][nt][3] + bsh[c + 1];
            *(float2*)(o0 + c) = s0;
            *(float2*)(o1 + c) = s1;
        }
    }
#undef ISSUE
}

// ===========================================================================
extern "C" void kernel_launch(void* const* d_in, const int* in_sizes, int n_in,
                              void* d_out, int out_size) {
    const float* x  = (const float*)d_in[0];
    const float* rw = (const float*)d_in[1];
    const float* rb = (const float*)d_in[2];
    const float* ew = (const float*)d_in[3];
    const float* eb = (const float*)d_in[4];
    const float* pw = (const float*)d_in[5];
    const float* pb = (const float*)d_in[6];

    float* out      = (float*)d_out;
    float* o_idx    = out;
    float* o_probs  = out + N_TOKENS;
    float* o_adapt  = o_probs + (size_t)N_TOKENS * N_TOOLS;
    float* o_params = o_adapt + (size_t)N_TOKENS * DIM;

    const int smem_sz = STAGES * SWORDS * 4 + BN * 4 + BM * 4;   // 83200 B
    cudaFuncSetAttribute(moe_gemm, cudaFuncAttributeMaxDynamicSharedMemorySize,
                         smem_sz);

    zero_counts_kernel<<<1, 64>>>();
    router_kernel<<<N_TOKENS / 64, 128>>>(x, rw, rb, o_idx, o_probs);
    build_tiles_kernel<<<1, 32>>>();
    moe_gemm<<<PCTAS + 2 * MAXTILES, NTHR, smem_sz>>>(x, pw, pb, ew, eb,
                                                      o_params, o_adapt);
}

// round 8
// speedup vs baseline: 2.8189x; 1.2809x over previous
#include <cuda_runtime.h>
#include <cstdint>

#define N_TOOLS 50
#define DIM 512
#define N_TOKENS 8192
#define PARAM_DIM 256

#define BM 64
#define BN 256
#define BK 16
#define STAGES 4
#define SWORDS ((BM + BN) * BK)      // 5120 words / stage
#define NTHR 256
#define PCTAS (N_TOKENS / BM)        // 128
#define MAXTILES 178
#define KITERS (DIM / BK)            // 32

// --------------------- device scratch (no allocs allowed) ------------------
__device__ int g_count[N_TOOLS];
__device__ int g_tokens[N_TOOLS * N_TOKENS];
__device__ int g_ntiles;
__device__ int g_tile_e[256];
__device__ int g_tile_m[256];

__global__ void zero_counts_kernel() {
    if (threadIdx.x < N_TOOLS) g_count[threadIdx.x] = 0;
}

// Parallel (expert, mtile) work-list build: 64-thread inclusive scan.
__global__ void build_tiles_kernel() {
    __shared__ int sc[64];
    const int e = threadIdx.x;
    const int t = (e < N_TOOLS) ? (g_count[e] + BM - 1) / BM : 0;
    sc[e] = t;
    __syncthreads();
#pragma unroll
    for (int s = 1; s < 64; s <<= 1) {
        int u = (e >= s) ? sc[e - s] : 0;
        __syncthreads();
        sc[e] += u;
        __syncthreads();
    }
    const int start = sc[e] - t;
    for (int i = 0; i < t; i++) {
        g_tile_e[start + i] = e;
        g_tile_m[start + i] = i;
    }
    if (e == 63) g_ntiles = sc[63];
}

// ----------------------------- helpers ------------------------------------
__device__ __forceinline__ uint32_t cvtu(uint32_t x) {
    uint32_t r;
    asm("cvt.rna.tf32.f32 %0, %1;" : "=r"(r) : "f"(__uint_as_float(x)));
    return r;
}
__device__ __forceinline__ void mma_tf32(float* c, uint32_t a0, uint32_t a1,
                                         uint32_t a2, uint32_t a3,
                                         uint32_t b0, uint32_t b1) {
    asm volatile(
        "mma.sync.aligned.m16n8k8.row.col.f32.tf32.tf32.f32 "
        "{%0,%1,%2,%3}, {%4,%5,%6,%7}, {%8,%9}, {%0,%1,%2,%3};"
        : "+f"(c[0]), "+f"(c[1]), "+f"(c[2]), "+f"(c[3])
        : "r"(a0), "r"(a1), "r"(a2), "r"(a3), "r"(b0), "r"(b1));
}
__device__ __forceinline__ uint32_t smem_u32(const void* p) {
    uint32_t a;
    asm("{ .reg .u64 t; cvta.to.shared.u64 t, %1; cvt.u32.u64 %0, t; }"
        : "=r"(a) : "l"(p));
    return a;
}
__device__ __forceinline__ void cp16(uint32_t dst, const float* src) {
    asm volatile("cp.async.cg.shared.global [%0], [%1], 16;"
                 :: "r"(dst), "l"(src) : "memory");
}
__device__ __forceinline__ void ldsm4(uint32_t& r0, uint32_t& r1, uint32_t& r2,
                                      uint32_t& r3, uint32_t addr) {
    asm volatile("ldmatrix.sync.aligned.m8n8.x4.shared.b16 {%0,%1,%2,%3}, [%4];"
                 : "=r"(r0), "=r"(r1), "=r"(r2), "=r"(r3) : "r"(addr));
}
#define CP_COMMIT() asm volatile("cp.async.commit_group;" ::: "memory")
#define CP_WAIT2()  asm volatile("cp.async.wait_group 2;" ::: "memory")

// ======================= router (exact fp32, k-split x2) ===================
// 256 blocks x 32 tokens, 128 threads: thread = (token, tool-half, k-half).
// Row stride 72 floats: second k-half starts at col 36 (byte 144, 16B-aligned).
#define RT_TOK 32
__global__ void __launch_bounds__(128)
router_kernel(const float* __restrict__ x, const float* __restrict__ rw,
              const float* __restrict__ rb, float* __restrict__ out_idx,
              float* __restrict__ out_probs) {
    __shared__ float Xs[RT_TOK][72];
    __shared__ float Ws[N_TOOLS][72];
    __shared__ float Ls[RT_TOK][2][52];
    __shared__ float Bs[64];

    const int tid = threadIdx.x;
    const int row0 = blockIdx.x * RT_TOK;
    if (tid < N_TOOLS) Bs[tid] = rb[tid];

    const int m = tid >> 2;
    const int th = tid & 1;
    const int kh = (tid >> 1) & 1;
    const int colb = kh * 36;

    float acc[25];
#pragma unroll
    for (int j = 0; j < 25; j++) acc[j] = 0.f;

    for (int s = 0; s < 8; s++) {
        const int k0 = s * 64;
        __syncthreads();
#pragma unroll
        for (int t = 0; t < 4; t++) {
            int j = tid + t * 128;
            int mm = j >> 4, kq = (j & 15) * 4;
            int col = ((kq >> 5) * 36) + (kq & 31);
            *(float4*)&Xs[mm][col] =
                *(const float4*)&x[(size_t)(row0 + mm) * DIM + k0 + kq];
        }
        for (int j = tid; j < 800; j += 128) {
            int n = j >> 4, kq = (j & 15) * 4;
            int col = ((kq >> 5) * 36) + (kq & 31);
            *(float4*)&Ws[n][col] =
                *(const float4*)&rw[(size_t)n * DIM + k0 + kq];
        }
        __syncthreads();
#pragma unroll
        for (int kk = 0; kk < 32; kk++) {
            float xv = Xs[m][colb + kk];
#pragma unroll
            for (int j = 0; j < 25; j++)
                acc[j] += xv * Ws[th * 25 + j][colb + kk];
        }
    }
#pragma unroll
    for (int j = 0; j < 25; j++) Ls[m][kh][th * 25 + j] = acc[j];
    __syncthreads();

    if (tid < RT_TOK) {
        const int row = row0 + tid;
        float lg[N_TOOLS];
        float best = -1e30f;
        int bi = 0;
#pragma unroll
        for (int j = 0; j < N_TOOLS; j++) {
            float v = Ls[tid][0][j] + Ls[tid][1][j] + Bs[j];
            lg[j] = v;
            if (v > best) { best = v; bi = j; }
        }
        float ssum = 0.f;
#pragma unroll
        for (int j = 0; j < N_TOOLS; j++) {
            lg[j] = expf(lg[j] - best);
            ssum += lg[j];
        }
        float inv = 1.f / ssum;
#pragma unroll
        for (int j = 0; j < N_TOOLS; j++)
            out_probs[(size_t)row * N_TOOLS + j] = lg[j] * inv;
        out_idx[row] = (float)bi;
        int pos = atomicAdd(&g_count[bi], 1);
        g_tokens[bi * N_TOKENS + pos] = row;
    }
}

// ================== merged tf32 tensor-core GEMM ===========================
// CTA: 64x256 tile, 256 thr / 8 warps, warp tile 32x64 (2m x 8n frags).
// cp.async 4-stage, BK=16, ldmatrix.x4 fragment loads (conflict-free under
// the chunk-XOR swizzle: chunk c of row r lives at chunk c ^ ((r>>1)&3)).
extern __shared__ uint32_t dynsm[];

__global__ void __launch_bounds__(NTHR, 2)
moe_gemm(const float* __restrict__ X, const float* __restrict__ pw,
         const float* __restrict__ pb, const float* __restrict__ ew,
         const float* __restrict__ eb, float* __restrict__ o_params,
         float* __restrict__ o_adapt) {
    float* bsh = (float*)(dynsm + STAGES * SWORDS);
    int* ridx = (int*)(bsh + BN);

    const int tid = threadIdx.x;
    const int lane = tid & 31, warp = tid >> 5;
    const int g = lane >> 2, tg = lane & 3;
    const int wm = (warp & 1) * 32;
    const int wn = (warp >> 1) * 64;

    const float* W;
    const float* bsrc;
    float* outbase;
    int out_ld, n0, row0 = 0;
    bool gather;

    if (blockIdx.x < PCTAS) {
        gather = false;
        row0 = blockIdx.x * BM;
        W = pw; bsrc = pb;
        outbase = o_params; out_ld = PARAM_DIM; n0 = 0;
    } else {
        gather = true;
        const int t = blockIdx.x - PCTAS;
        const int ty = t >> 1;
        if (ty >= g_ntiles) return;
        n0 = (t & 1) * BN;
        const int e = g_tile_e[ty];
        const int mtile = g_tile_m[ty];
        const int cnt = g_count[e];
        W = ew + (size_t)e * DIM * DIM + (size_t)n0 * DIM;
        bsrc = eb + (size_t)e * DIM + n0;
        outbase = o_adapt; out_ld = DIM;
        if (tid < BM) {
            int p = mtile * BM + tid;
            ridx[tid] = g_tokens[e * N_TOKENS + (p < cnt ? p : cnt - 1)];
        }
    }
    if (tid < BN) bsh[tid] = bsrc[tid];
    __syncthreads();

    // ---- cp.async setup: thread -> A row r0 (1 chunk) + B rows r0+64j ----
    const uint32_t smbase = smem_u32(dynsm);
    const int r0 = tid >> 2, q = tid & 3;
    const uint32_t dstA =
        smbase + ((uint32_t)(r0 * 16 + ((q ^ ((r0 >> 1) & 3)) << 2)) << 2);
    const int ar0 = gather ? ridx[r0] : row0 + r0;
    const float* srcA = X + (size_t)ar0 * DIM + q * 4;
    const float* srcB = W + (size_t)r0 * DIM + q * 4;

#define ISSUE(s, ko) do {                                                    \
        uint32_t d = (uint32_t)(s) * (SWORDS * 4);                           \
        cp16(dstA + d, srcA + (ko));                                         \
        _Pragma("unroll")                                                    \
        for (int j = 0; j < 4; j++)                                          \
            cp16(dstA + d + 4096 + j * 4096, srcB + j * (64 * DIM) + (ko));  \
        CP_COMMIT();                                                         \
    } while (0)

    ISSUE(0, 0);
    ISSUE(1, BK);
    ISSUE(2, 2 * BK);

    // ---- ldmatrix address precompute ----
    const int j8 = lane >> 3, lr = lane & 7;
    uint32_t aadr[2][2], badr[4][2];
#pragma unroll
    for (int mt = 0; mt < 2; mt++)
#pragma unroll
        for (int h = 0; h < 2; h++) {
            int r = wm + mt * 16 + ((j8 & 1) << 3) + lr;
            int c = 2 * h + (j8 >> 1);
            aadr[mt][h] =
                smbase + ((uint32_t)(r * 16 + ((c ^ ((r >> 1) & 3)) << 2)) << 2);
        }
#pragma unroll
    for (int np = 0; np < 4; np++)
#pragma unroll
        for (int h = 0; h < 2; h++) {
            int r = BM + wn + np * 16 + ((j8 >> 1) << 3) + lr;
            int c = 2 * h + (j8 & 1);
            badr[np][h] =
                smbase + ((uint32_t)(r * 16 + ((c ^ ((r >> 1) & 3)) << 2)) << 2);
        }

    float acc[2][8][4];
#pragma unroll
    for (int mt = 0; mt < 2; mt++)
#pragma unroll
        for (int nt = 0; nt < 8; nt++)
#pragma unroll
            for (int i = 0; i < 4; i++) acc[mt][nt][i] = 0.f;

    for (int kt = 0; kt < KITERS; kt++) {
        CP_WAIT2();
        __syncthreads();
        if (kt + 3 < KITERS) {
            ISSUE((kt + 3) & 3, (kt + 3) * BK);
        } else {
            CP_COMMIT();
        }
        const uint32_t so = (uint32_t)(kt & 3) * (SWORDS * 4);

#pragma unroll
        for (int h = 0; h < 2; h++) {
            uint32_t a[2][4];
#pragma unroll
            for (int mt = 0; mt < 2; mt++) {
                uint32_t t0, t1, t2, t3;
                ldsm4(t0, t1, t2, t3, aadr[mt][h] + so);
                a[mt][0] = cvtu(t0); a[mt][1] = cvtu(t1);
                a[mt][2] = cvtu(t2); a[mt][3] = cvtu(t3);
            }
#pragma unroll
            for (int np = 0; np < 4; np++) {
                uint32_t b0, b1, b2, b3;
                ldsm4(b0, b1, b2, b3, badr[np][h] + so);
                b0 = cvtu(b0); b1 = cvtu(b1); b2 = cvtu(b2); b3 = cvtu(b3);
#pragma unroll
                for (int mt = 0; mt < 2; mt++) {
                    mma_tf32(acc[mt][2 * np], a[mt][0], a[mt][1], a[mt][2],
                             a[mt][3], b0, b1);
                    mma_tf32(acc[mt][2 * np + 1], a[mt][0], a[mt][1], a[mt][2],
                             a[mt][3], b2, b3);
                }
            }
        }
    }

    // ---- epilogue: bias + store (padded duplicate rows write identical
    //      values -> deterministic) ----
#pragma unroll
    for (int mt = 0; mt < 2; mt++) {
        const int lr0 = wm + mt * 16 + g;
        const int lr1 = lr0 + 8;
        const int gr0 = gather ? ridx[lr0] : row0 + lr0;
        const int gr1 = gather ? ridx[lr1] : row0 + lr1;
        float* o0 = outbase + (size_t)gr0 * out_ld + n0;
        float* o1 = outbase + (size_t)gr1 * out_ld + n0;
#pragma unroll
        for (int nt = 0; nt < 8; nt++) {
            const int c = wn + nt * 8 + 2 * tg;
            float2 s0, s1;
            s0.x = acc[mt][nt][0] + bsh[c];
            s0.y = acc[mt][nt][1] + bsh[c + 1];
            s1.x = acc[mt][nt][2] + bsh[c];
            s1.y = acc[mt][nt][3] + bsh[c + 1];
            *(float2*)(o0 + c) = s0;
            *(float2*)(o1 + c) = s1;
        }
    }
#undef ISSUE
}

// ===========================================================================
extern "C" void kernel_launch(void* const* d_in, const int* in_sizes, int n_in,
                              void* d_out, int out_size) {
    const float* x  = (const float*)d_in[0];
    const float* rw = (const float*)d_in[1];
    const float* rb = (const float*)d_in[2];
    const float* ew = (const float*)d_in[3];
    const float* eb = (const float*)d_in[4];
    const float* pw = (const float*)d_in[5];
    const float* pb = (const float*)d_in[6];

    float* out      = (float*)d_out;
    float* o_idx    = out;
    float* o_probs  = out + N_TOKENS;
    float* o_adapt  = o_probs + (size_t)N_TOKENS * N_TOOLS;
    float* o_params = o_adapt + (size_t)N_TOKENS * DIM;

    const int smem_sz = STAGES * SWORDS * 4 + BN * 4 + BM * 4;   // 83200 B
    cudaFuncSetAttribute(moe_gemm, cudaFuncAttributeMaxDynamicSharedMemorySize,
                         smem_sz);

    zero_counts_kernel<<<1, 64>>>();
    router_kernel<<<N_TOKENS / RT_TOK, 128>>>(x, rw, rb, o_idx, o_probs);
    build_tiles_kernel<<<1, 64>>>();
    moe_gemm<<<PCTAS + 2 * MAXTILES, NTHR, smem_sz>>>(x, pw, pb, ew, eb,
                                                      o_params, o_adapt);
}

// round 10
// speedup vs baseline: 2.8832x; 1.0228x over previous
#include <cuda_runtime.h>
#include <cstdint>

#define N_TOOLS 50
#define DIM 512
#define N_TOKENS 8192
#define PARAM_DIM 256

#define BM 64
#define BN 256
#define BK 16
#define SWORDS ((BM + BN) * BK)      // fp32 stage: 5120 words = 20KB
#define HWORDS ((BM + BN) * 8)       // fp16 buf: 2560 words = 10KB
#define HBASE  (4 * SWORDS)          // fp16 bufs after 4 fp32 stages
#define NTHR 256
#define PCTAS (N_TOKENS / BM)        // 128
#define MAXTILES 178
#define KITERS (DIM / BK)            // 32

// --------------------- device scratch (no allocs allowed) ------------------
__device__ int g_count[N_TOOLS];     // zero-initialized; re-zeroed each call
__device__ int g_tokens[N_TOOLS * N_TOKENS];
__device__ int g_ntiles;
__device__ int g_tile_e[256];
__device__ int g_tile_m[256];
__device__ int g_tile_cnt[256];

// Parallel work-list build + g_count restore (keeps zero-invariant so no
// separate zeroing kernel is needed).
__global__ void build_tiles_kernel() {
    __shared__ int sc[64];
    const int e = threadIdx.x;
    const int c = (e < N_TOOLS) ? g_count[e] : 0;
    const int t = (c + BM - 1) / BM;
    sc[e] = t;
    __syncthreads();
#pragma unroll
    for (int s = 1; s < 64; s <<= 1) {
        int u = (e >= s) ? sc[e - s] : 0;
        __syncthreads();
        sc[e] += u;
        __syncthreads();
    }
    const int start = sc[e] - t;
    for (int i = 0; i < t; i++) {
        g_tile_e[start + i] = e;
        g_tile_m[start + i] = i;
        g_tile_cnt[start + i] = c;
    }
    if (e == 63) g_ntiles = sc[63];
    if (e < N_TOOLS) g_count[e] = 0;
}

// ----------------------------- helpers ------------------------------------
__device__ __forceinline__ uint32_t pack_f16x2(float lo, float hi) {
    uint32_t r;  // first PTX src -> upper half
    asm("cvt.rn.f16x2.f32 %0, %1, %2;" : "=r"(r) : "f"(hi), "f"(lo));
    return r;
}
__device__ __forceinline__ void mma_f16(float* c, uint32_t a0, uint32_t a1,
                                        uint32_t a2, uint32_t a3,
                                        uint32_t b0, uint32_t b1) {
    asm volatile(
        "mma.sync.aligned.m16n8k16.row.col.f32.f16.f16.f32 "
        "{%0,%1,%2,%3}, {%4,%5,%6,%7}, {%8,%9}, {%0,%1,%2,%3};"
        : "+f"(c[0]), "+f"(c[1]), "+f"(c[2]), "+f"(c[3])
        : "r"(a0), "r"(a1), "r"(a2), "r"(a3), "r"(b0), "r"(b1));
}
__device__ __forceinline__ uint32_t smem_u32(const void* p) {
    uint32_t a;
    asm("{ .reg .u64 t; cvta.to.shared.u64 t, %1; cvt.u32.u64 %0, t; }"
        : "=r"(a) : "l"(p));
    return a;
}
__device__ __forceinline__ void cp16(uint32_t dst, const float* src) {
    asm volatile("cp.async.cg.shared.global [%0], [%1], 16;"
                 :: "r"(dst), "l"(src) : "memory");
}
__device__ __forceinline__ void ldsm4(uint32_t& r0, uint32_t& r1, uint32_t& r2,
                                      uint32_t& r3, uint32_t addr) {
    asm volatile("ldmatrix.sync.aligned.m8n8.x4.shared.b16 {%0,%1,%2,%3}, [%4];"
                 : "=r"(r0), "=r"(r1), "=r"(r2), "=r"(r3) : "r"(addr));
}
#define CP_COMMIT() asm volatile("cp.async.commit_group;" ::: "memory")
#define CP_WAIT(n)  asm volatile("cp.async.wait_group %0;" :: "n"(n) : "memory")

// fp16 tile layout: row r (0..319) has 16 halves = 2 16B chunks.
// byte = (r>>3)*256 + slot*16,  slot = ((r&7)<<1) | (c ^ ((r>>2)&1))
// Bijective over each 8-row x 2-chunk group.  For an ldsm phase (8 aligned
// rows, fixed c) banks are (8*(r&7) + 4*bit) mod 32 with bit flipping
// between r and r+4 -> all 8 reads hit distinct 4-bank groups: CF.
__device__ __forceinline__ int h_off(int r, int c) {
    return ((r >> 3) << 8) + ((((r & 7) << 1) | (c ^ ((r >> 2) & 1))) << 4);
}

// ======================= router (exact fp32, k-split x2) ===================
#define RT_TOK 32
__global__ void __launch_bounds__(128)
router_kernel(const float* __restrict__ x, const float* __restrict__ rw,
              const float* __restrict__ rb, float* __restrict__ out_idx,
              float* __restrict__ out_probs) {
    __shared__ float Xs[RT_TOK][72];
    __shared__ float Ws[N_TOOLS][72];
    __shared__ float Ls[RT_TOK][2][52];
    __shared__ float Bs[64];

    const int tid = threadIdx.x;
    const int row0 = blockIdx.x * RT_TOK;
    if (tid < N_TOOLS) Bs[tid] = rb[tid];

    const int m = tid >> 2;
    const int th = tid & 1;
    const int kh = (tid >> 1) & 1;
    const int colb = kh * 36;

    float acc[25];
#pragma unroll
    for (int j = 0; j < 25; j++) acc[j] = 0.f;

    for (int s = 0; s < 8; s++) {
        const int k0 = s * 64;
        __syncthreads();
#pragma unroll
        for (int t = 0; t < 4; t++) {
            int j = tid + t * 128;
            int mm = j >> 4, kq = (j & 15) * 4;
            int col = ((kq >> 5) * 36) + (kq & 31);
            *(float4*)&Xs[mm][col] =
                *(const float4*)&x[(size_t)(row0 + mm) * DIM + k0 + kq];
        }
        for (int j = tid; j < 800; j += 128) {
            int n = j >> 4, kq = (j & 15) * 4;
            int col = ((kq >> 5) * 36) + (kq & 31);
            *(float4*)&Ws[n][col] =
                *(const float4*)&rw[(size_t)n * DIM + k0 + kq];
        }
        __syncthreads();
#pragma unroll
        for (int kk = 0; kk < 32; kk++) {
            float xv = Xs[m][colb + kk];
#pragma unroll
            for (int j = 0; j < 25; j++)
                acc[j] += xv * Ws[th * 25 + j][colb + kk];
        }
    }
#pragma unroll
    for (int j = 0; j < 25; j++) Ls[m][kh][th * 25 + j] = acc[j];
    __syncthreads();

    if (tid < RT_TOK) {
        const int row = row0 + tid;
        float lg[N_TOOLS];
        float best = -1e30f;
        int bi = 0;
#pragma unroll
        for (int j = 0; j < N_TOOLS; j++) {
            float v = Ls[tid][0][j] + Ls[tid][1][j] + Bs[j];
            lg[j] = v;
            if (v > best) { best = v; bi = j; }
        }
        float ssum = 0.f;
#pragma unroll
        for (int j = 0; j < N_TOOLS; j++) {
            lg[j] = expf(lg[j] - best);
            ssum += lg[j];
        }
        float inv = 1.f / ssum;
#pragma unroll
        for (int j = 0; j < N_TOOLS; j++)
            out_probs[(size_t)row * N_TOOLS + j] = lg[j] * inv;
        out_idx[row] = (float)bi;
        int pos = atomicAdd(&g_count[bi], 1);
        g_tokens[bi * N_TOKENS + pos] = row;
    }
}

// ================== merged fp16 tensor-core GEMM ===========================
// CTA: 64x256 tile, 256 thr / 8 warps, warp tile 32x64.
// cp.async fp32 4-stage -> cooperative fp32->fp16 convert (1 kt ahead,
// double-buffered) -> ldmatrix.b16 -> mma.m16n8k16.f16 (2x tf32 rate).
extern __shared__ uint32_t dynsm[];

__global__ void __launch_bounds__(NTHR, 2)
moe_gemm(const float* __restrict__ X, const float* __restrict__ pw,
         const float* __restrict__ pb, const float* __restrict__ ew,
         const float* __restrict__ eb, float* __restrict__ o_params,
         float* __restrict__ o_adapt) {
    float* bsh = (float*)(dynsm + HBASE + 2 * HWORDS);
    int* ridx = (int*)(bsh + BN);

    const int tid = threadIdx.x;
    const int lane = tid & 31, warp = tid >> 5;
    const int g = lane >> 2, tg = lane & 3;
    const int wm = (warp & 1) * 32;
    const int wn = (warp >> 1) * 64;

    const float* W;
    const float* bsrc;
    float* outbase;
    int out_ld, n0, row0 = 0;
    bool gather;

    if (blockIdx.x < PCTAS) {
        gather = false;
        row0 = blockIdx.x * BM;
        W = pw; bsrc = pb;
        outbase = o_params; out_ld = PARAM_DIM; n0 = 0;
    } else {
        gather = true;
        const int t = blockIdx.x - PCTAS;
        const int ty = t >> 1;
        if (ty >= g_ntiles) return;
        n0 = (t & 1) * BN;
        const int e = g_tile_e[ty];
        const int mtile = g_tile_m[ty];
        const int cnt = g_tile_cnt[ty];
        W = ew + (size_t)e * DIM * DIM + (size_t)n0 * DIM;
        bsrc = eb + (size_t)e * DIM + n0;
        outbase = o_adapt; out_ld = DIM;
        if (tid < BM) {
            int p = mtile * BM + tid;
            ridx[tid] = g_tokens[e * N_TOKENS + (p < cnt ? p : cnt - 1)];
        }
    }
    if (tid < BN) bsh[tid] = bsrc[tid];
    __syncthreads();

    // ---- cp.async setup (fp32): thread -> A row r0 chunk q + B rows ----
    const uint32_t smbase = smem_u32(dynsm);
    const int r0 = tid >> 2, q = tid & 3;
    const uint32_t dstA =
        smbase + ((uint32_t)(r0 * 16 + ((q ^ ((r0 >> 1) & 3)) << 2)) << 2);
    const int ar0 = gather ? ridx[r0] : row0 + r0;
    const float* srcA = X + (size_t)ar0 * DIM + q * 4;
    const float* srcB = W + (size_t)r0 * DIM + q * 4;

#define ISSUE(s, ko) do {                                                    \
        uint32_t d = (uint32_t)(s) * (SWORDS * 4);                           \
        cp16(dstA + d, srcA + (ko));                                         \
        _Pragma("unroll")                                                    \
        for (int j = 0; j < 4; j++)                                          \
            cp16(dstA + d + 4096 + j * 4096, srcB + j * (64 * DIM) + (ko));  \
        CP_COMMIT();                                                         \
    } while (0)

    // ---- convert-pass setup: 5 (row, quad) slots per thread ----
    int cw32[5];   // fp32 word offset (LDS.128)
    int ch16[5];   // fp16 byte offset (STS.64)
#pragma unroll
    for (int i = 0; i < 5; i++) {
        int id = tid + 256 * i;
        int r = id >> 2, cq = id & 3;
        cw32[i] = r * 16 + ((cq ^ ((r >> 1) & 3)) << 2);
        ch16[i] = h_off(r, cq >> 1) + (cq & 1) * 8;
    }
    const uint32_t hb16 = smbase + HBASE * 4;

#define CONVERT(kt) do {                                                     \
        const uint32_t* Sf = dynsm + ((kt) & 3) * SWORDS;                    \
        uint32_t hd = hb16 + ((kt) & 1) * (HWORDS * 4);                      \
        _Pragma("unroll")                                                    \
        for (int i = 0; i < 5; i++) {                                        \
            float4 v = *(const float4*)&Sf[cw32[i]];                         \
            uint32_t u0 = pack_f16x2(v.x, v.y);                              \
            uint32_t u1 = pack_f16x2(v.z, v.w);                              \
            asm volatile("st.shared.v2.b32 [%0], {%1, %2};"                  \
                         :: "r"(hd + ch16[i]), "r"(u0), "r"(u1) : "memory"); \
        }                                                                    \
    } while (0)

    // ---- ldmatrix addresses (fp16 buffers) ----
    const int j8 = lane >> 3, lr = lane & 7;
    uint32_t aadr[2], badr[4];
#pragma unroll
    for (int mt = 0; mt < 2; mt++) {
        int r = wm + mt * 16 + ((j8 & 1) << 3) + lr;
        aadr[mt] = hb16 + h_off(r, j8 >> 1);
    }
#pragma unroll
    for (int np = 0; np < 4; np++) {
        int r = BM + wn + np * 16 + ((j8 & 1) << 3) + lr;
        badr[np] = hb16 + h_off(r, j8 >> 1);
    }

    float acc[2][8][4];
#pragma unroll
    for (int mt = 0; mt < 2; mt++)
#pragma unroll
        for (int nt = 0; nt < 8; nt++)
#pragma unroll
            for (int i = 0; i < 4; i++) acc[mt][nt][i] = 0.f;

    // ---- prologue ----
    ISSUE(0, 0);
    ISSUE(1, BK);
    ISSUE(2, 2 * BK);
    CP_WAIT(2);
    __syncthreads();
    CONVERT(0);

    for (int kt = 0; kt < KITERS; kt++) {
        if (kt + 1 < KITERS) CP_WAIT(1);   // stage kt+1 landed
        __syncthreads();                   // convert(kt) + stage kt+1 visible
        if (kt + 1 < KITERS) CONVERT(kt + 1);
        if (kt + 3 < KITERS) ISSUE((kt + 3) & 3, (kt + 3) * BK);

        const uint32_t ho = (uint32_t)(kt & 1) * (HWORDS * 4);
        uint32_t a[2][4];
#pragma unroll
        for (int mt = 0; mt < 2; mt++)
            ldsm4(a[mt][0], a[mt][1], a[mt][2], a[mt][3], aadr[mt] + ho);
#pragma unroll
        for (int np = 0; np < 4; np++) {
            uint32_t b0, b1, b2, b3;
            ldsm4(b0, b1, b2, b3, badr[np] + ho);
#pragma unroll
            for (int mt = 0; mt < 2; mt++) {
                mma_f16(acc[mt][2 * np], a[mt][0], a[mt][1], a[mt][2],
                        a[mt][3], b0, b2);
                mma_f16(acc[mt][2 * np + 1], a[mt][0], a[mt][1], a[mt][2],
                        a[mt][3], b1, b3);
            }
        }
    }

    // ---- epilogue: bias + store (padded duplicate rows write identical
    //      values -> deterministic) ----
#pragma unroll
    for (int mt = 0; mt < 2; mt++) {
        const int lr0 = wm + mt * 16 + g;
        const int lr1 = lr0 + 8;
        const int gr0 = gather ? ridx[lr0] : row0 + lr0;
        const int gr1 = gather ? ridx[lr1] : row0 + lr1;
        float* o0 = outbase + (size_t)gr0 * out_ld + n0;
        float* o1 = outbase + (size_t)gr1 * out_ld + n0;
#pragma unroll
        for (int nt = 0; nt < 8; nt++) {
            const int c = wn + nt * 8 + 2 * tg;
            float2 s0, s1;
            s0.x = acc[mt][nt][0] + bsh[c];
            s0.y = acc[mt][nt][1] + bsh[c + 1];
            s1.x = acc[mt][nt][2] + bsh[c];
            s1.y = acc[mt][nt][3] + bsh[c + 1];
            *(float2*)(o0 + c) = s0;
            *(float2*)(o1 + c) = s1;
        }
    }
#undef ISSUE
#undef CONVERT
}

// ===========================================================================
extern "C" void kernel_launch(void* const* d_in, const int* in_sizes, int n_in,
                              void* d_out, int out_size) {
    const float* x  = (const float*)d_in[0];
    const float* rw = (const float*)d_in[1];
    const float* rb = (const float*)d_in[2];
    const float* ew = (const float*)d_in[3];
    const float* eb = (const float*)d_in[4];
    const float* pw = (const float*)d_in[5];
    const float* pb = (const float*)d_in[6];

    float* out      = (float*)d_out;
    float* o_idx    = out;
    float* o_probs  = out + N_TOKENS;
    float* o_adapt  = o_probs + (size_t)N_TOKENS * N_TOOLS;
    float* o_params = o_adapt + (size_t)N_TOKENS * DIM;

    // 4 fp32 stages (80KB) + 2 fp16 bufs (20KB) + bias + ridx
    const int smem_sz = (HBASE + 2 * HWORDS) * 4 + BN * 4 + BM * 4;
    cudaFuncSetAttribute(moe_gemm, cudaFuncAttributeMaxDynamicSharedMemorySize,
                         smem_sz);

    router_kernel<<<N_TOKENS / RT_TOK, 128>>>(x, rw, rb, o_idx, o_probs);
    build_tiles_kernel<<<1, 64>>>();
    moe_gemm<<<PCTAS + 2 * MAXTILES, NTHR, smem_sz>>>(x, pw, pb, ew, eb,
                                                      o_params, o_adapt);
}

// round 12
// speedup vs baseline: 3.7297x; 1.2936x over previous
#include <cuda_runtime.h>
#include <cstdint>

#define N_TOOLS 50
#define DIM 512
#define N_TOKENS 8192
#define PARAM_DIM 256

#define BM 64
#define BN 256
#define BK 16
#define SWORDS ((BM + BN) * BK)      // fp32 stage: 5120 words = 20KB
#define HWORDS ((BM + BN) * 8)       // fp16 buf: 2560 words = 10KB
#define HBASE  (4 * SWORDS)          // fp16 bufs after 4 fp32 stages
#define NTHR 256
#define PCTAS (N_TOKENS / BM)        // 128
#define MAXTILES 178
#define KITERS (DIM / BK)            // 32

// --------------------- device scratch (no allocs allowed) ------------------
__device__ int g_count[N_TOOLS];     // zero-initialized; re-zeroed each call
__device__ int g_tokens[N_TOOLS * N_TOKENS];
__device__ int g_ntiles;
__device__ int g_tile_e[256];
__device__ int g_tile_m[256];
__device__ int g_tile_cnt[256];

// Parallel work-list build + g_count restore (keeps zero-invariant so no
// separate zeroing kernel is needed).
__global__ void build_tiles_kernel() {
    __shared__ int sc[64];
    const int e = threadIdx.x;
    const int c = (e < N_TOOLS) ? g_count[e] : 0;
    const int t = (c + BM - 1) / BM;
    sc[e] = t;
    __syncthreads();
#pragma unroll
    for (int s = 1; s < 64; s <<= 1) {
        int u = (e >= s) ? sc[e - s] : 0;
        __syncthreads();
        sc[e] += u;
        __syncthreads();
    }
    const int start = sc[e] - t;
    for (int i = 0; i < t; i++) {
        g_tile_e[start + i] = e;
        g_tile_m[start + i] = i;
        g_tile_cnt[start + i] = c;
    }
    if (e == 63) g_ntiles = sc[63];
    if (e < N_TOOLS) g_count[e] = 0;
}

// ----------------------------- helpers ------------------------------------
__device__ __forceinline__ uint32_t pack_f16x2(float lo, float hi) {
    uint32_t r;  // first PTX src -> upper half
    asm("cvt.rn.f16x2.f32 %0, %1, %2;" : "=r"(r) : "f"(hi), "f"(lo));
    return r;
}
__device__ __forceinline__ void mma_f16(float* c, uint32_t a0, uint32_t a1,
                                        uint32_t a2, uint32_t a3,
                                        uint32_t b0, uint32_t b1) {
    asm volatile(
        "mma.sync.aligned.m16n8k16.row.col.f32.f16.f16.f32 "
        "{%0,%1,%2,%3}, {%4,%5,%6,%7}, {%8,%9}, {%0,%1,%2,%3};"
        : "+f"(c[0]), "+f"(c[1]), "+f"(c[2]), "+f"(c[3])
        : "r"(a0), "r"(a1), "r"(a2), "r"(a3), "r"(b0), "r"(b1));
}
__device__ __forceinline__ uint32_t smem_u32(const void* p) {
    uint32_t a;
    asm("{ .reg .u64 t; cvta.to.shared.u64 t, %1; cvt.u32.u64 %0, t; }"
        : "=r"(a) : "l"(p));
    return a;
}
__device__ __forceinline__ void cp16(uint32_t dst, const float* src) {
    asm volatile("cp.async.cg.shared.global [%0], [%1], 16;"
                 :: "r"(dst), "l"(src) : "memory");
}
__device__ __forceinline__ void ldsm4(uint32_t& r0, uint32_t& r1, uint32_t& r2,
                                      uint32_t& r3, uint32_t addr) {
    asm volatile("ldmatrix.sync.aligned.m8n8.x4.shared.b16 {%0,%1,%2,%3}, [%4];"
                 : "=r"(r0), "=r"(r1), "=r"(r2), "=r"(r3) : "r"(addr));
}
#define CP_COMMIT() asm volatile("cp.async.commit_group;" ::: "memory")
#define CP_WAIT(n)  asm volatile("cp.async.wait_group %0;" :: "n"(n) : "memory")

// fp16 tile layout: byte = (r>>3)*256 + slot*16,
// slot = ((r&7)<<1) | (c ^ ((r>>2)&1))  (bijective per 8-row group; ldsm CF)
__device__ __forceinline__ int h_off(int r, int c) {
    return ((r >> 3) << 8) + ((((r & 7) << 1) | (c ^ ((r >> 2) & 1))) << 4);
}

// ======================= router (exact fp32) ==============================
// 256 blocks x 32 tokens, 256 threads: tid = p(4b)|h(1b)|s(3b).
// Thread: tokens {2p,2p+1}, tools [25h,25h+25), k in {32c + 4s + kk}.
// Per kk: 27 LDS / 50 FFMA.  k-split reduced via shfl_xor on lane bits 0-2.
// W tile = 800 float2 -> 3 full loader passes + 1 partial (tid<32, rows 48-49).
#define RT_M 32
__global__ void __launch_bounds__(256)
router_kernel(const float* __restrict__ x, const float* __restrict__ rw,
              const float* __restrict__ rb, float* __restrict__ out_idx,
              float* __restrict__ out_probs) {
    __shared__ float Xs[RT_M * 34];
    __shared__ float Ws[N_TOOLS * 34];
    __shared__ float Ls[RT_M][52];
    __shared__ float Bs[52];

    const int tid = threadIdx.x;
    const int row0 = blockIdx.x * RT_M;
    if (tid < N_TOOLS) Bs[tid] = rb[tid];

    const int s = tid & 7;
    const int h = (tid >> 3) & 1;
    const int p = tid >> 4;

    // loader element -> (row = e>>4, float2 col = e&15)
    const int xr0 = tid >> 4,          xc0 = (tid & 15) << 1;
    const int xr1 = (tid + 256) >> 4;
    const int wr0 = xr0, wr1 = xr1;
    const int wr2 = (tid + 512) >> 4;                 // rows 32..47
    const int wr3 = (tid + 768) >> 4;                 // rows 48..49
    const bool w3ok = tid < 32;                       // 800 float2 total

    const float* xp0 = x + (size_t)(row0 + xr0) * DIM + xc0;
    const float* xp1 = x + (size_t)(row0 + xr1) * DIM + xc0;
    const float* wp0 = rw + (size_t)wr0 * DIM + xc0;
    const float* wp1 = rw + (size_t)wr1 * DIM + xc0;
    const float* wp2 = rw + (size_t)wr2 * DIM + xc0;
    const float* wp3 = rw + (size_t)wr3 * DIM + xc0;

    float2 px0, px1, pw0, pw1, pw2, pw3;
    px0 = *(const float2*)(xp0);
    px1 = *(const float2*)(xp1);
    pw0 = *(const float2*)(wp0);
    pw1 = *(const float2*)(wp1);
    pw2 = *(const float2*)(wp2);
    pw3 = w3ok ? *(const float2*)(wp3) : make_float2(0.f, 0.f);

    float a0[25], a1[25];
#pragma unroll
    for (int j = 0; j < 25; j++) { a0[j] = 0.f; a1[j] = 0.f; }

    const int xb0 = (2 * p) * 34 + s * 4;
    const int xb1 = xb0 + 34;
    const int wb = (h * 25) * 34 + s * 4;

    for (int c = 0; c < 16; c++) {
        __syncthreads();
        *(float2*)&Xs[xr0 * 34 + xc0] = px0;
        *(float2*)&Xs[xr1 * 34 + xc0] = px1;
        *(float2*)&Ws[wr0 * 34 + xc0] = pw0;
        *(float2*)&Ws[wr1 * 34 + xc0] = pw1;
        *(float2*)&Ws[wr2 * 34 + xc0] = pw2;
        if (w3ok) *(float2*)&Ws[wr3 * 34 + xc0] = pw3;
        __syncthreads();
        if (c + 1 < 16) {
            const int ko = (c + 1) * 32;
            px0 = *(const float2*)(xp0 + ko);
            px1 = *(const float2*)(xp1 + ko);
            pw0 = *(const float2*)(wp0 + ko);
            pw1 = *(const float2*)(wp1 + ko);
            pw2 = *(const float2*)(wp2 + ko);
            if (w3ok) pw3 = *(const float2*)(wp3 + ko);
        }
#pragma unroll
        for (int kk = 0; kk < 4; kk++) {
            const float x0 = Xs[xb0 + kk];
            const float x1 = Xs[xb1 + kk];
#pragma unroll
            for (int j = 0; j < 25; j++) {
                const float w = Ws[wb + j * 34 + kk];
                a0[j] += x0 * w;
                a1[j] += x1 * w;
            }
        }
    }

    // reduce across k-splits (s = lane bits 0-2)
#pragma unroll
    for (int j = 0; j < 25; j++) {
#pragma unroll
        for (int d = 1; d < 8; d <<= 1) {
            a0[j] += __shfl_xor_sync(0xffffffffu, a0[j], d);
            a1[j] += __shfl_xor_sync(0xffffffffu, a1[j], d);
        }
    }
    if (s == 0) {
#pragma unroll
        for (int j = 0; j < 25; j++) {
            Ls[2 * p][h * 25 + j] = a0[j];
            Ls[2 * p + 1][h * 25 + j] = a1[j];
        }
    }
    __syncthreads();

    if (tid < RT_M) {
        const int row = row0 + tid;
        float lg[N_TOOLS];
        float best = -1e30f;
        int bi = 0;
#pragma unroll
        for (int j = 0; j < N_TOOLS; j++) {
            float v = Ls[tid][j] + Bs[j];
            lg[j] = v;
            if (v > best) { best = v; bi = j; }
        }
        float ssum = 0.f;
#pragma unroll
        for (int j = 0; j < N_TOOLS; j++) {
            lg[j] = expf(lg[j] - best);
            ssum += lg[j];
        }
        float inv = 1.f / ssum;
#pragma unroll
        for (int j = 0; j < N_TOOLS; j++)
            out_probs[(size_t)row * N_TOOLS + j] = lg[j] * inv;
        out_idx[row] = (float)bi;
        int pos = atomicAdd(&g_count[bi], 1);
        g_tokens[bi * N_TOKENS + pos] = row;
    }
}

// ================== merged fp16 tensor-core GEMM (unchanged) ===============
extern __shared__ uint32_t dynsm[];

__global__ void __launch_bounds__(NTHR, 2)
moe_gemm(const float* __restrict__ X, const float* __restrict__ pw,
         const float* __restrict__ pb, const float* __restrict__ ew,
         const float* __restrict__ eb, float* __restrict__ o_params,
         float* __restrict__ o_adapt) {
    float* bsh = (float*)(dynsm + HBASE + 2 * HWORDS);
    int* ridx = (int*)(bsh + BN);

    const int tid = threadIdx.x;
    const int lane = tid & 31, warp = tid >> 5;
    const int g = lane >> 2, tg = lane & 3;
    const int wm = (warp & 1) * 32;
    const int wn = (warp >> 1) * 64;

    const float* W;
    const float* bsrc;
    float* outbase;
    int out_ld, n0, row0 = 0;
    bool gather;

    if (blockIdx.x < PCTAS) {
        gather = false;
        row0 = blockIdx.x * BM;
        W = pw; bsrc = pb;
        outbase = o_params; out_ld = PARAM_DIM; n0 = 0;
    } else {
        gather = true;
        const int t = blockIdx.x - PCTAS;
        const int ty = t >> 1;
        if (ty >= g_ntiles) return;
        n0 = (t & 1) * BN;
        const int e = g_tile_e[ty];
        const int mtile = g_tile_m[ty];
        const int cnt = g_tile_cnt[ty];
        W = ew + (size_t)e * DIM * DIM + (size_t)n0 * DIM;
        bsrc = eb + (size_t)e * DIM + n0;
        outbase = o_adapt; out_ld = DIM;
        if (tid < BM) {
            int p = mtile * BM + tid;
            ridx[tid] = g_tokens[e * N_TOKENS + (p < cnt ? p : cnt - 1)];
        }
    }
    if (tid < BN) bsh[tid] = bsrc[tid];
    __syncthreads();

    const uint32_t smbase = smem_u32(dynsm);
    const int r0 = tid >> 2, q = tid & 3;
    const uint32_t dstA =
        smbase + ((uint32_t)(r0 * 16 + ((q ^ ((r0 >> 1) & 3)) << 2)) << 2);
    const int ar0 = gather ? ridx[r0] : row0 + r0;
    const float* srcA = X + (size_t)ar0 * DIM + q * 4;
    const float* srcB = W + (size_t)r0 * DIM + q * 4;

#define ISSUE(s, ko) do {                                                    \
        uint32_t d = (uint32_t)(s) * (SWORDS * 4);                           \
        cp16(dstA + d, srcA + (ko));                                         \
        _Pragma("unroll")                                                    \
        for (int j = 0; j < 4; j++)                                          \
            cp16(dstA + d + 4096 + j * 4096, srcB + j * (64 * DIM) + (ko));  \
        CP_COMMIT();                                                         \
    } while (0)

    int cw32[5];
    int ch16[5];
#pragma unroll
    for (int i = 0; i < 5; i++) {
        int id = tid + 256 * i;
        int r = id >> 2, cq = id & 3;
        cw32[i] = r * 16 + ((cq ^ ((r >> 1) & 3)) << 2);
        ch16[i] = h_off(r, cq >> 1) + (cq & 1) * 8;
    }
    const uint32_t hb16 = smbase + HBASE * 4;

#define CONVERT(kt) do {                                                     \
        const uint32_t* Sf = dynsm + ((kt) & 3) * SWORDS;                    \
        uint32_t hd = hb16 + ((kt) & 1) * (HWORDS * 4);                      \
        _Pragma("unroll")                                                    \
        for (int i = 0; i < 5; i++) {                                        \
            float4 v = *(const float4*)&Sf[cw32[i]];                         \
            uint32_t u0 = pack_f16x2(v.x, v.y);                              \
            uint32_t u1 = pack_f16x2(v.z, v.w);                              \
            asm volatile("st.shared.v2.b32 [%0], {%1, %2};"                  \
                         :: "r"(hd + ch16[i]), "r"(u0), "r"(u1) : "memory"); \
        }                                                                    \
    } while (0)

    const int j8 = lane >> 3, lr = lane & 7;
    uint32_t aadr[2], badr[4];
#pragma unroll
    for (int mt = 0; mt < 2; mt++) {
        int r = wm + mt * 16 + ((j8 & 1) << 3) + lr;
        aadr[mt] = hb16 + h_off(r, j8 >> 1);
    }
#pragma unroll
    for (int np = 0; np < 4; np++) {
        int r = BM + wn + np * 16 + ((j8 & 1) << 3) + lr;
        badr[np] = hb16 + h_off(r, j8 >> 1);
    }

    float acc[2][8][4];
#pragma unroll
    for (int mt = 0; mt < 2; mt++)
#pragma unroll
        for (int nt = 0; nt < 8; nt++)
#pragma unroll
            for (int i = 0; i < 4; i++) acc[mt][nt][i] = 0.f;

    ISSUE(0, 0);
    ISSUE(1, BK);
    ISSUE(2, 2 * BK);
    CP_WAIT(2);
    __syncthreads();
    CONVERT(0);

    for (int kt = 0; kt < KITERS; kt++) {
        if (kt + 1 < KITERS) CP_WAIT(1);
        __syncthreads();
        if (kt + 1 < KITERS) CONVERT(kt + 1);
        if (kt + 3 < KITERS) ISSUE((kt + 3) & 3, (kt + 3) * BK);

        const uint32_t ho = (uint32_t)(kt & 1) * (HWORDS * 4);
        uint32_t a[2][4];
#pragma unroll
        for (int mt = 0; mt < 2; mt++)
            ldsm4(a[mt][0], a[mt][1], a[mt][2], a[mt][3], aadr[mt] + ho);
#pragma unroll
        for (int np = 0; np < 4; np++) {
            uint32_t b0, b1, b2, b3;
            ldsm4(b0, b1, b2, b3, badr[np] + ho);
#pragma unroll
            for (int mt = 0; mt < 2; mt++) {
                mma_f16(acc[mt][2 * np], a[mt][0], a[mt][1], a[mt][2],
                        a[mt][3], b0, b2);
                mma_f16(acc[mt][2 * np + 1], a[mt][0], a[mt][1], a[mt][2],
                        a[mt][3], b1, b3);
            }
        }
    }

#pragma unroll
    for (int mt = 0; mt < 2; mt++) {
        const int lr0 = wm + mt * 16 + g;
        const int lr1 = lr0 + 8;
        const int gr0 = gather ? ridx[lr0] : row0 + lr0;
        const int gr1 = gather ? ridx[lr1] : row0 + lr1;
        float* o0 = outbase + (size_t)gr0 * out_ld + n0;
        float* o1 = outbase + (size_t)gr1 * out_ld + n0;
#pragma unroll
        for (int nt = 0; nt < 8; nt++) {
            const int c = wn + nt * 8 + 2 * tg;
            float2 s0, s1;
            s0.x = acc[mt][nt][0] + bsh[c];
            s0.y = acc[mt][nt][1] + bsh[c + 1];
            s1.x = acc[mt][nt][2] + bsh[c];
            s1.y = acc[mt][nt][3] + bsh[c + 1];
            *(float2*)(o0 + c) = s0;
            *(float2*)(o1 + c) = s1;
        }
    }
#undef ISSUE
#undef CONVERT
}

// ===========================================================================
extern "C" void kernel_launch(void* const* d_in, const int* in_sizes, int n_in,
                              void* d_out, int out_size) {
    const float* x  = (const float*)d_in[0];
    const float* rw = (const float*)d_in[1];
    const float* rb = (const float*)d_in[2];
    const float* ew = (const float*)d_in[3];
    const float* eb = (const float*)d_in[4];
    const float* pw = (const float*)d_in[5];
    const float* pb = (const float*)d_in[6];

    float* out      = (float*)d_out;
    float* o_idx    = out;
    float* o_probs  = out + N_TOKENS;
    float* o_adapt  = o_probs + (size_t)N_TOKENS * N_TOOLS;
    float* o_params = o_adapt + (size_t)N_TOKENS * DIM;

    const int smem_sz = (HBASE + 2 * HWORDS) * 4 + BN * 4 + BM * 4;
    cudaFuncSetAttribute(moe_gemm, cudaFuncAttributeMaxDynamicSharedMemorySize,
                         smem_sz);

    router_kernel<<<N_TOKENS / RT_M, 256>>>(x, rw, rb, o_idx, o_probs);
    build_tiles_kernel<<<1, 64>>>();
    moe_gemm<<<PCTAS + 2 * MAXTILES, NTHR, smem_sz>>>(x, pw, pb, ew, eb,
                                                      o_params, o_adapt);
}